// round 13
// baseline (speedup 1.0000x reference)
#include <cuda_runtime.h>
#include <cstdint>

#define NTOK 64
#define EPS 1e-5f

// ---- shared memory layout (float offsets) ----
#define ST_STRIDE 257
#define OFF_T   0                 // sT  [64][257] = 16448
#define OFF_O   16448             // sO  [64][257] = 16448
#define OFF_B   32896             // sB  weight tile, 8192 floats (32KB)
#define OFF_SCR 41088             // scratch (union)
#define SQ_OFF  (OFF_SCR)             // [64][33] = 2112
#define SK_OFF  (OFF_SCR + 2112)      // [64][33] = 2112
#define SV_OFF  (OFF_SCR + 4224)      // [64][34] = 2176
#define SS_OFF  (OFF_SCR + 6400)      // [64][65] = 4160  (ends at 51648)
#define SH_OFF  (OFF_SCR)             // [64][132] = 8448 (union with sQ..sS)
#define OFF_P   51648             // params: bq,bk,bv,g1,be1,g2,be2 (7*256)
#define SMEM_FLOATS 53440
#define SMEM_BYTES  (SMEM_FLOATS * 4)

__global__ __launch_bounds__(256, 1)
void win_attn_kernel(const float* __restrict__ x, const float* __restrict__ src,
                     const float* __restrict__ Wq, const float* __restrict__ bq,
                     const float* __restrict__ Wk, const float* __restrict__ bk,
                     const float* __restrict__ Wv, const float* __restrict__ bv,
                     const float* __restrict__ Wm, const float* __restrict__ W1,
                     const float* __restrict__ W2, const float* __restrict__ g1,
                     const float* __restrict__ be1, const float* __restrict__ g2,
                     const float* __restrict__ be2, float* __restrict__ out)
{
    extern __shared__ float sm[];
    float* sT = sm + OFF_T;
    float* sO = sm + OFF_O;
    float* sB = sm + OFF_B;
    float* sQ = sm + SQ_OFF;
    float* sK = sm + SK_OFF;
    float* sV = sm + SV_OFF;
    float* sS = sm + SS_OFF;
    float* sH = sm + SH_OFF;
    float* sBq  = sm + OFF_P;
    float* sBk  = sBq + 256;
    float* sBv  = sBq + 512;
    float* sG1  = sBq + 768;
    float* sBe1 = sBq + 1024;
    float* sG2  = sBq + 1280;
    float* sBe2 = sBq + 1536;

    const int tid = threadIdx.x;
    const int w   = blockIdx.x;          // 0..4095; first 2048 = x windows, rest = source
    const int tensor = w >> 11;
    const int local  = w & 2047;
    const int bb = local >> 10;
    const int wy = (local >> 5) & 31;
    const int wx = local & 31;
    const float* __restrict__ in = tensor ? src : x;

    // preload params (256 threads, one element each per array)
    sBq[tid]  = bq[tid];  sBk[tid]  = bk[tid];  sBv[tid] = bv[tid];
    sG1[tid]  = g1[tid];  sBe1[tid] = be1[tid];
    sG2[tid]  = g2[tid];  sBe2[tid] = be2[tid];

    // ---- Phase 0: gather window -> sT[n][c] ----
    {
        const int n  = tid & 63;
        const int cg = tid >> 6;
        const int gy = wy * 8 + (n >> 3);
        const int gx = wx * 8 + (n & 7);
        const float* base = in + ((size_t)bb * 256 * 65536) + (size_t)gy * 256 + gx;
        #pragma unroll 4
        for (int c = cg * 64; c < cg * 64 + 64; ++c)
            sT[n * ST_STRIDE + c] = base[(size_t)c * 65536];
    }
    __syncthreads();

    const int ty = tid >> 4;   // 0..15 -> rows ty*4 .. ty*4+3
    const int tx = tid & 15;   // 0..15 -> column groups

    // ---- Phase 1: per-head attention ----
    for (int h = 0; h < 8; ++h) {
        const int hs = h * 32;

        // (a) qkv = t @ [Wq|Wk|Wv][:, hs:hs+32] + bias  -> [64, 96]
        float acc[4][6];
        #pragma unroll
        for (int j = 0; j < 6; ++j) {
            int cc = tx * 6 + j;
            float bias = (cc < 32) ? sBq[hs + cc]
                       : (cc < 64) ? sBk[hs + (cc & 31)]
                                   : sBv[hs + (cc & 31)];
            #pragma unroll
            for (int i = 0; i < 4; ++i) acc[i][j] = bias;
        }
        for (int kt = 0; kt < 4; ++kt) {
            __syncthreads();
            for (int l = tid; l < 64 * 96; l += 256) {
                int kk = l / 96, cc = l % 96;
                const float* W = (cc < 32) ? Wq : (cc < 64) ? Wk : Wv;
                sB[l] = W[(kt * 64 + kk) * 256 + hs + (cc & 31)];
            }
            __syncthreads();
            #pragma unroll 4
            for (int kk = 0; kk < 64; ++kk) {
                const int ka = kt * 64 + kk;
                float a[4];
                #pragma unroll
                for (int i = 0; i < 4; ++i) a[i] = sT[(ty * 4 + i) * ST_STRIDE + ka];
                #pragma unroll
                for (int jj = 0; jj < 3; ++jj) {
                    float2 b2 = *(const float2*)&sB[kk * 96 + tx * 6 + jj * 2];
                    #pragma unroll
                    for (int i = 0; i < 4; ++i) {
                        acc[i][jj * 2]     += a[i] * b2.x;
                        acc[i][jj * 2 + 1] += a[i] * b2.y;
                    }
                }
            }
        }
        // scatter to padded q/k/v buffers
        #pragma unroll
        for (int j = 0; j < 6; ++j) {
            int cc = tx * 6 + j;
            #pragma unroll
            for (int i = 0; i < 4; ++i) {
                int row = ty * 4 + i;
                if (cc < 32)      sQ[row * 33 + cc]        = acc[i][j];
                else if (cc < 64) sK[row * 33 + (cc - 32)] = acc[i][j];
                else              sV[row * 34 + (cc - 64)] = acc[i][j];
            }
        }
        __syncthreads();

        // (b) scores = q @ k^T  [64,64], K=32 (no 1/sqrt(hd) scaling, faithful)
        {
            float sc[4][4];
            #pragma unroll
            for (int i = 0; i < 4; ++i)
                #pragma unroll
                for (int j = 0; j < 4; ++j) sc[i][j] = 0.f;
            #pragma unroll 8
            for (int k = 0; k < 32; ++k) {
                float a[4], b[4];
                #pragma unroll
                for (int i = 0; i < 4; ++i) a[i] = sQ[(ty * 4 + i) * 33 + k];
                #pragma unroll
                for (int j = 0; j < 4; ++j) b[j] = sK[(tx * 4 + j) * 33 + k];
                #pragma unroll
                for (int i = 0; i < 4; ++i)
                    #pragma unroll
                    for (int j = 0; j < 4; ++j) sc[i][j] += a[i] * b[j];
            }
            #pragma unroll
            for (int i = 0; i < 4; ++i)
                #pragma unroll
                for (int j = 0; j < 4; ++j)
                    sS[(ty * 4 + i) * 65 + tx * 4 + j] = sc[i][j];
        }
        __syncthreads();

        // softmax over rows (4 lanes per row, 16 cols each)
        {
            const int r  = tid >> 2;
            const int c0 = (tid & 3) * 16;
            float e[16];
            float mx = -1e30f;
            #pragma unroll
            for (int j = 0; j < 16; ++j) { e[j] = sS[r * 65 + c0 + j]; mx = fmaxf(mx, e[j]); }
            mx = fmaxf(mx, __shfl_xor_sync(0xffffffffu, mx, 1));
            mx = fmaxf(mx, __shfl_xor_sync(0xffffffffu, mx, 2));
            float s = 0.f;
            #pragma unroll
            for (int j = 0; j < 16; ++j) { e[j] = __expf(e[j] - mx); s += e[j]; }
            s += __shfl_xor_sync(0xffffffffu, s, 1);
            s += __shfl_xor_sync(0xffffffffu, s, 2);
            float inv = 1.f / s;
            #pragma unroll
            for (int j = 0; j < 16; ++j) sS[r * 65 + c0 + j] = e[j] * inv;
        }
        __syncthreads();

        // (c) o_h = attn @ v  [64,32] -> sO[:, hs:hs+32]
        {
            float oc[4][2];
            #pragma unroll
            for (int i = 0; i < 4; ++i) { oc[i][0] = 0.f; oc[i][1] = 0.f; }
            #pragma unroll 8
            for (int k = 0; k < 64; ++k) {
                float a[4];
                #pragma unroll
                for (int i = 0; i < 4; ++i) a[i] = sS[(ty * 4 + i) * 65 + k];
                float2 b2 = *(const float2*)&sV[k * 34 + tx * 2];
                #pragma unroll
                for (int i = 0; i < 4; ++i) {
                    oc[i][0] += a[i] * b2.x;
                    oc[i][1] += a[i] * b2.y;
                }
            }
            #pragma unroll
            for (int i = 0; i < 4; ++i) {
                int row = ty * 4 + i;
                sO[row * ST_STRIDE + hs + tx * 2]     = oc[i][0];
                sO[row * ST_STRIDE + hs + tx * 2 + 1] = oc[i][1];
            }
        }
        // next head's first tile-load __syncthreads() orders these writes
    }
    __syncthreads();

    // ---- Phase 2: M = sO @ Wm  -> LN1 -> back into sO ----
    {
        float acc[4][4][4];
        #pragma unroll
        for (int i = 0; i < 4; ++i)
            #pragma unroll
            for (int q = 0; q < 4; ++q)
                #pragma unroll
                for (int j = 0; j < 4; ++j) acc[i][q][j] = 0.f;

        for (int kt = 0; kt < 8; ++kt) {
            __syncthreads();
            const float4* gsrc = (const float4*)(Wm + kt * 32 * 256);
            float4* dst = (float4*)sB;
            for (int f = tid; f < 2048; f += 256) dst[f] = gsrc[f];
            __syncthreads();
            #pragma unroll 2
            for (int kk = 0; kk < 32; ++kk) {
                float a[4];
                #pragma unroll
                for (int i = 0; i < 4; ++i)
                    a[i] = sO[(ty * 4 + i) * ST_STRIDE + kt * 32 + kk];
                #pragma unroll
                for (int q = 0; q < 4; ++q) {
                    float4 b4 = *(const float4*)&sB[kk * 256 + tx * 4 + 64 * q];
                    #pragma unroll
                    for (int i = 0; i < 4; ++i) {
                        acc[i][q][0] += a[i] * b4.x;
                        acc[i][q][1] += a[i] * b4.y;
                        acc[i][q][2] += a[i] * b4.z;
                        acc[i][q][3] += a[i] * b4.w;
                    }
                }
            }
        }
        __syncthreads();   // all reads of sO done before overwrite

        #pragma unroll
        for (int i = 0; i < 4; ++i) {
            float s1 = 0.f;
            #pragma unroll
            for (int q = 0; q < 4; ++q)
                #pragma unroll
                for (int j = 0; j < 4; ++j) s1 += acc[i][q][j];
            #pragma unroll
            for (int m = 1; m <= 8; m <<= 1) s1 += __shfl_xor_sync(0xffffffffu, s1, m);
            float mean = s1 * (1.f / 256.f);
            float s2 = 0.f;
            #pragma unroll
            for (int q = 0; q < 4; ++q)
                #pragma unroll
                for (int j = 0; j < 4; ++j) { float d = acc[i][q][j] - mean; s2 += d * d; }
            #pragma unroll
            for (int m = 1; m <= 8; m <<= 1) s2 += __shfl_xor_sync(0xffffffffu, s2, m);
            float rstd = rsqrtf(s2 * (1.f / 256.f) + EPS);
            int row = ty * 4 + i;
            #pragma unroll
            for (int q = 0; q < 4; ++q)
                #pragma unroll
                for (int j = 0; j < 4; ++j) {
                    int col = tx * 4 + 64 * q + j;
                    sO[row * ST_STRIDE + col] =
                        (acc[i][q][j] - mean) * rstd * sG1[col] + sBe1[col];
                }
        }
        __syncthreads();
    }

    // ---- Phase 3: MLP  Y = relu(cat[t, LN1] @ W1) @ W2 ; out = t + LN2(Y) ----
    {
        float y[4][4][4];
        #pragma unroll
        for (int i = 0; i < 4; ++i)
            #pragma unroll
            for (int q = 0; q < 4; ++q)
                #pragma unroll
                for (int j = 0; j < 4; ++j) y[i][q][j] = 0.f;

        for (int ht = 0; ht < 4; ++ht) {
            // (i) Htile = relu(cat @ W1[:, ht*128 : ht*128+128])
            float ha[4][2][4];
            #pragma unroll
            for (int i = 0; i < 4; ++i)
                #pragma unroll
                for (int q = 0; q < 2; ++q)
                    #pragma unroll
                    for (int j = 0; j < 4; ++j) ha[i][q][j] = 0.f;

            for (int kt = 0; kt < 16; ++kt) {
                __syncthreads();
                for (int f = tid; f < 1024; f += 256) {
                    int kk = f >> 5, c4 = f & 31;
                    ((float4*)sB)[f] =
                        *(const float4*)&W1[(kt * 32 + kk) * 512 + ht * 128 + c4 * 4];
                }
                __syncthreads();
                const float* A = (kt < 8) ? sT : sO;
                const int kbase = (kt < 8) ? kt * 32 : (kt - 8) * 32;
                #pragma unroll 2
                for (int kk = 0; kk < 32; ++kk) {
                    float a[4];
                    #pragma unroll
                    for (int i = 0; i < 4; ++i)
                        a[i] = A[(ty * 4 + i) * ST_STRIDE + kbase + kk];
                    #pragma unroll
                    for (int q = 0; q < 2; ++q) {
                        float4 b4 = *(const float4*)&sB[kk * 128 + tx * 4 + 64 * q];
                        #pragma unroll
                        for (int i = 0; i < 4; ++i) {
                            ha[i][q][0] += a[i] * b4.x;
                            ha[i][q][1] += a[i] * b4.y;
                            ha[i][q][2] += a[i] * b4.z;
                            ha[i][q][3] += a[i] * b4.w;
                        }
                    }
                }
            }
            __syncthreads();   // previous (ii) reads of sH are ordered long before
            #pragma unroll
            for (int i = 0; i < 4; ++i) {
                int row = ty * 4 + i;
                #pragma unroll
                for (int q = 0; q < 2; ++q) {
                    float4 hv;
                    hv.x = fmaxf(ha[i][q][0], 0.f);
                    hv.y = fmaxf(ha[i][q][1], 0.f);
                    hv.z = fmaxf(ha[i][q][2], 0.f);
                    hv.w = fmaxf(ha[i][q][3], 0.f);
                    *(float4*)&sH[row * 132 + tx * 4 + 64 * q] = hv;
                }
            }
            __syncthreads();

            // (ii) Y += Htile @ W2[ht*128 : ht*128+128, :]
            for (int kt2 = 0; kt2 < 4; ++kt2) {
                __syncthreads();
                const float4* gsrc = (const float4*)(W2 + (ht * 128 + kt2 * 32) * 256);
                for (int f = tid; f < 2048; f += 256) ((float4*)sB)[f] = gsrc[f];
                __syncthreads();
                #pragma unroll 2
                for (int kk = 0; kk < 32; ++kk) {
                    float a[4];
                    #pragma unroll
                    for (int i = 0; i < 4; ++i)
                        a[i] = sH[(ty * 4 + i) * 132 + kt2 * 32 + kk];
                    #pragma unroll
                    for (int q = 0; q < 4; ++q) {
                        float4 b4 = *(const float4*)&sB[kk * 256 + tx * 4 + 64 * q];
                        #pragma unroll
                        for (int i = 0; i < 4; ++i) {
                            y[i][q][0] += a[i] * b4.x;
                            y[i][q][1] += a[i] * b4.y;
                            y[i][q][2] += a[i] * b4.z;
                            y[i][q][3] += a[i] * b4.w;
                        }
                    }
                }
            }
        }

        // LN2 + residual + store
        const size_t gbase = (size_t)w * 16384;
        #pragma unroll
        for (int i = 0; i < 4; ++i) {
            float s1 = 0.f;
            #pragma unroll
            for (int q = 0; q < 4; ++q)
                #pragma unroll
                for (int j = 0; j < 4; ++j) s1 += y[i][q][j];
            #pragma unroll
            for (int m = 1; m <= 8; m <<= 1) s1 += __shfl_xor_sync(0xffffffffu, s1, m);
            float mean = s1 * (1.f / 256.f);
            float s2 = 0.f;
            #pragma unroll
            for (int q = 0; q < 4; ++q)
                #pragma unroll
                for (int j = 0; j < 4; ++j) { float d = y[i][q][j] - mean; s2 += d * d; }
            #pragma unroll
            for (int m = 1; m <= 8; m <<= 1) s2 += __shfl_xor_sync(0xffffffffu, s2, m);
            float rstd = rsqrtf(s2 * (1.f / 256.f) + EPS);
            int row = ty * 4 + i;
            #pragma unroll
            for (int q = 0; q < 4; ++q) {
                float4 o4;
                #pragma unroll
                for (int j = 0; j < 4; ++j) {
                    int col = tx * 4 + 64 * q + j;
                    float v = (y[i][q][j] - mean) * rstd * sG2[col] + sBe2[col]
                              + sT[row * ST_STRIDE + col];
                    ((float*)&o4)[j] = v;
                }
                *(float4*)&out[gbase + (size_t)row * 256 + tx * 4 + 64 * q] = o4;
            }
        }
    }
}

// writes the scalar tail outputs (nums_window=1024, h=256, w=256) if present
__global__ void tail_kernel(float* __restrict__ out, long long base, int extra)
{
    if (threadIdx.x == 0) {
        const float vals[3] = {1024.f, 256.f, 256.f};
        for (int i = 0; i < extra; ++i) out[base + i] = vals[i];
    }
}

extern "C" void kernel_launch(void* const* d_in, const int* in_sizes, int n_in,
                              void* d_out, int out_size)
{
    (void)in_sizes; (void)n_in;
    const float* x   = (const float*)d_in[0];
    const float* src = (const float*)d_in[1];
    const float* Wq  = (const float*)d_in[2];
    const float* bq  = (const float*)d_in[3];
    const float* Wk  = (const float*)d_in[4];
    const float* bk  = (const float*)d_in[5];
    const float* Wv  = (const float*)d_in[6];
    const float* bv  = (const float*)d_in[7];
    const float* Wm  = (const float*)d_in[8];
    const float* W1  = (const float*)d_in[9];
    const float* W2  = (const float*)d_in[10];
    const float* g1  = (const float*)d_in[11];
    const float* be1 = (const float*)d_in[12];
    const float* g2  = (const float*)d_in[13];
    const float* be2 = (const float*)d_in[14];
    float* out = (float*)d_out;

    cudaFuncSetAttribute(win_attn_kernel,
                         cudaFuncAttributeMaxDynamicSharedMemorySize, SMEM_BYTES);

    const long long base = 4096LL * 16384LL;   // 2 * 2048 windows * 64 * 256
    if ((long long)out_size >= base) {
        win_attn_kernel<<<4096, 256, SMEM_BYTES>>>(
            x, src, Wq, bq, Wk, bk, Wv, bv, Wm, W1, W2, g1, be1, g2, be2, out);
        long long extra = (long long)out_size - base;
        if (extra > 0) {
            if (extra > 3) extra = 3;
            tail_kernel<<<1, 32>>>(out, base, (int)extra);
        }
    }
}

// round 14
// speedup vs baseline: 2.0123x; 2.0123x over previous
#include <cuda_runtime.h>
#include <cstdint>

#define EPS 1e-5f
#define STS 260   // sT/sO row stride (260 mod 32 == 4 -> conflict-free A-fragment loads)

// ---- shared memory layout (float offsets) ----
#define OFF_T   0                     // sT [64][260] = 16640
#define OFF_O   16640                 // sO [64][260] = 16640
#define OFF_B   33280                 // sB weight staging, 8192 floats (32KB)
#define OFF_SCR 41472                 // scratch union (10560 floats)
#define SQ_OFF  (OFF_SCR)             // [64][33] = 2112
#define SK_OFF  (OFF_SCR + 2112)      // [64][33] = 2112
#define SV_OFF  (OFF_SCR + 4224)      // [64][34] = 2176
#define SS_OFF  (OFF_SCR + 6400)      // [64][65] = 4160 (ends 52032)
#define SH_OFF  (OFF_SCR)             // [64][132] = 8448 (union)
#define OFF_P   52032                 // bq,bk,bv,g1,be1,g2,be2 (7*256)
#define SMEM_FLOATS 53824
#define SMEM_BYTES  (SMEM_FLOATS * 4)

__device__ __forceinline__ uint32_t f2tf(float f) {
    uint32_t u;
    asm("cvt.rna.tf32.f32 %0, %1;" : "=r"(u) : "f"(f));
    return u;
}

// D += A(16x8,row) * B(8x8,col)  tf32, fp32 accumulate
__device__ __forceinline__ void mma8(float* d,
                                     uint32_t a0, uint32_t a1, uint32_t a2, uint32_t a3,
                                     uint32_t b0, uint32_t b1) {
    asm volatile(
        "mma.sync.aligned.m16n8k8.row.col.f32.tf32.tf32.f32 "
        "{%0,%1,%2,%3}, {%4,%5,%6,%7}, {%8,%9}, {%0,%1,%2,%3};\n"
        : "+f"(d[0]), "+f"(d[1]), "+f"(d[2]), "+f"(d[3])
        : "r"(a0), "r"(a1), "r"(a2), "r"(a3), "r"(b0), "r"(b1));
}

// Stage a [KS*8, NT*8] tile of row-major W (ld=ldw) at (kbase,nbase) into sB in
// fragment order: slot p = ((ks*NT + nt)*32 + lane) holds {B[k0][n], B[k0+4][n]}
// with k0 = ks*8 + (lane&3), n = nt*8 + (lane>>2), converted to tf32.
__device__ __forceinline__ void stageB(float* sB, const float* __restrict__ W, int ldw,
                                       int kbase, int nbase, int KS, int NT, int tid) {
    uint2* dst = (uint2*)sB;
    const int total = KS * NT * 32;
    for (int p = tid; p < total; p += 256) {
        int ln = p & 31, rest = p >> 5;
        int nt = rest % NT, ks = rest / NT;
        int k = kbase + ks * 8 + (ln & 3);
        int n = nbase + nt * 8 + (ln >> 2);
        uint2 v;
        v.x = f2tf(W[k * ldw + n]);
        v.y = f2tf(W[(k + 4) * ldw + n]);
        dst[p] = v;
    }
}

__global__ __launch_bounds__(256, 1)
void win_attn_kernel(const float* __restrict__ x, const float* __restrict__ src,
                     const float* __restrict__ Wq, const float* __restrict__ bq,
                     const float* __restrict__ Wk, const float* __restrict__ bk,
                     const float* __restrict__ Wv, const float* __restrict__ bv,
                     const float* __restrict__ Wm, const float* __restrict__ W1,
                     const float* __restrict__ W2, const float* __restrict__ g1,
                     const float* __restrict__ be1, const float* __restrict__ g2,
                     const float* __restrict__ be2, float* __restrict__ out)
{
    extern __shared__ float sm[];
    float* sT = sm + OFF_T;
    float* sO = sm + OFF_O;
    float* sB = sm + OFF_B;
    float* sQ = sm + SQ_OFF;
    float* sK = sm + SK_OFF;
    float* sV = sm + SV_OFF;
    float* sS = sm + SS_OFF;
    float* sH = sm + SH_OFF;
    float* sBq  = sm + OFF_P;
    float* sBk  = sBq + 256;
    float* sBv  = sBq + 512;
    float* sG1  = sBq + 768;
    float* sBe1 = sBq + 1024;
    float* sG2  = sBq + 1280;
    float* sBe2 = sBq + 1536;

    const int tid  = threadIdx.x;
    const int warp = tid >> 5;
    const int lane = tid & 31;
    const int gid  = lane >> 2;   // row group 0..7
    const int ctid = lane & 3;    // k/col sub-id 0..3
    const int m0   = (warp & 3) * 16;  // m16 strip base
    const int nh   = warp >> 2;        // n-half 0/1

    const int w   = blockIdx.x;
    const int tensor = w >> 11;
    const int local  = w & 2047;
    const int bb = local >> 10;
    const int wy = (local >> 5) & 31;
    const int wx = local & 31;
    const float* __restrict__ in = tensor ? src : x;

    sBq[tid]  = bq[tid];  sBk[tid]  = bk[tid];  sBv[tid] = bv[tid];
    sG1[tid]  = g1[tid];  sBe1[tid] = be1[tid];
    sG2[tid]  = g2[tid];  sBe2[tid] = be2[tid];

    // ---- Phase 0: gather window -> sT[n][c] ----
    {
        const int n  = tid & 63;
        const int cg = tid >> 6;
        const int gy = wy * 8 + (n >> 3);
        const int gx = wx * 8 + (n & 7);
        const float* base = in + ((size_t)bb * 256 * 65536) + (size_t)gy * 256 + gx;
        #pragma unroll 4
        for (int c = cg * 64; c < cg * 64 + 64; ++c)
            sT[n * STS + c] = base[(size_t)c * 65536];
    }
    __syncthreads();

    const int ty = tid >> 4;
    const int tx = tid & 15;

    // ---- Phase 1: per-head attention ----
    for (int h = 0; h < 8; ++h) {
        const int hs = h * 32;

        // (a) qkv = t @ [Wq|Wk|Wv][:, hs:hs+32]  via tf32 mma, 12 n8-tiles (96 cols)
        float dq[6][4];
        #pragma unroll
        for (int a = 0; a < 6; ++a)
            #pragma unroll
            for (int e = 0; e < 4; ++e) dq[a][e] = 0.f;

        for (int chunk = 0; chunk < 4; ++chunk) {   // k-chunks of 64
            __syncthreads();
            for (int p = tid; p < 8 * 12 * 32; p += 256) {
                int ln = p & 31, rest = p >> 5;
                int nt = rest % 12, ks = rest / 12;
                int k  = chunk * 64 + ks * 8 + (ln & 3);
                int cc = nt * 8 + (ln >> 2);
                const float* Wp; int wc;
                if (cc < 32)      { Wp = Wq; wc = hs + cc; }
                else if (cc < 64) { Wp = Wk; wc = hs + cc - 32; }
                else              { Wp = Wv; wc = hs + cc - 64; }
                uint2 v;
                v.x = f2tf(Wp[k * 256 + wc]);
                v.y = f2tf(Wp[(k + 4) * 256 + wc]);
                ((uint2*)sB)[p] = v;
            }
            __syncthreads();
            #pragma unroll
            for (int ks = 0; ks < 8; ++ks) {
                const int kc = chunk * 64 + ks * 8;
                const float* Ap = sT + (m0 + gid) * STS + kc + ctid;
                uint32_t a0 = f2tf(Ap[0]);
                uint32_t a1 = f2tf(Ap[8 * STS]);
                uint32_t a2 = f2tf(Ap[4]);
                uint32_t a3 = f2tf(Ap[8 * STS + 4]);
                #pragma unroll
                for (int ntl = 0; ntl < 6; ++ntl) {
                    int nt = nh * 6 + ntl;
                    uint2 b = ((const uint2*)sB)[(ks * 12 + nt) * 32 + lane];
                    mma8(dq[ntl], a0, a1, a2, a3, b.x, b.y);
                }
            }
        }
        // scatter D (+bias) to padded q/k/v buffers
        {
            const int r0 = m0 + gid, r1 = r0 + 8;
            #pragma unroll
            for (int ntl = 0; ntl < 6; ++ntl) {
                int cc0 = (nh * 6 + ntl) * 8 + ctid * 2;
                #pragma unroll
                for (int e = 0; e < 4; ++e) {
                    int row = (e < 2) ? r0 : r1;
                    int cc  = cc0 + (e & 1);
                    float v = dq[ntl][e];
                    if (cc < 32)      sQ[row * 33 + cc]        = v + sBq[hs + cc];
                    else if (cc < 64) sK[row * 33 + (cc - 32)] = v + sBk[hs + cc - 32];
                    else              sV[row * 34 + (cc - 64)] = v + sBv[hs + cc - 64];
                }
            }
        }
        __syncthreads();

        // (b) scores = q @ k^T  [64,64], K=32 (fp32, faithful no-scale)
        {
            float sc[4][4];
            #pragma unroll
            for (int i = 0; i < 4; ++i)
                #pragma unroll
                for (int j = 0; j < 4; ++j) sc[i][j] = 0.f;
            #pragma unroll 8
            for (int k = 0; k < 32; ++k) {
                float a[4], b[4];
                #pragma unroll
                for (int i = 0; i < 4; ++i) a[i] = sQ[(ty * 4 + i) * 33 + k];
                #pragma unroll
                for (int j = 0; j < 4; ++j) b[j] = sK[(tx * 4 + j) * 33 + k];
                #pragma unroll
                for (int i = 0; i < 4; ++i)
                    #pragma unroll
                    for (int j = 0; j < 4; ++j) sc[i][j] += a[i] * b[j];
            }
            #pragma unroll
            for (int i = 0; i < 4; ++i)
                #pragma unroll
                for (int j = 0; j < 4; ++j)
                    sS[(ty * 4 + i) * 65 + tx * 4 + j] = sc[i][j];
        }
        __syncthreads();

        // softmax over rows
        {
            const int r  = tid >> 2;
            const int c0 = (tid & 3) * 16;
            float e[16];
            float mx = -1e30f;
            #pragma unroll
            for (int j = 0; j < 16; ++j) { e[j] = sS[r * 65 + c0 + j]; mx = fmaxf(mx, e[j]); }
            mx = fmaxf(mx, __shfl_xor_sync(0xffffffffu, mx, 1));
            mx = fmaxf(mx, __shfl_xor_sync(0xffffffffu, mx, 2));
            float s = 0.f;
            #pragma unroll
            for (int j = 0; j < 16; ++j) { e[j] = __expf(e[j] - mx); s += e[j]; }
            s += __shfl_xor_sync(0xffffffffu, s, 1);
            s += __shfl_xor_sync(0xffffffffu, s, 2);
            float inv = 1.f / s;
            #pragma unroll
            for (int j = 0; j < 16; ++j) sS[r * 65 + c0 + j] = e[j] * inv;
        }
        __syncthreads();

        // (c) o_h = attn @ v  [64,32] -> sO[:, hs:hs+32]  (fp32)
        {
            float oc[4][2];
            #pragma unroll
            for (int i = 0; i < 4; ++i) { oc[i][0] = 0.f; oc[i][1] = 0.f; }
            #pragma unroll 8
            for (int k = 0; k < 64; ++k) {
                float a[4];
                #pragma unroll
                for (int i = 0; i < 4; ++i) a[i] = sS[(ty * 4 + i) * 65 + k];
                float2 b2 = *(const float2*)&sV[k * 34 + tx * 2];
                #pragma unroll
                for (int i = 0; i < 4; ++i) {
                    oc[i][0] += a[i] * b2.x;
                    oc[i][1] += a[i] * b2.y;
                }
            }
            #pragma unroll
            for (int i = 0; i < 4; ++i) {
                int row = ty * 4 + i;
                sO[row * STS + hs + tx * 2]     = oc[i][0];
                sO[row * STS + hs + tx * 2 + 1] = oc[i][1];
            }
        }
        // next head's first staging __syncthreads() orders these writes
    }
    __syncthreads();

    // ---- Phase 2: M = sO @ Wm -> LN1 -> back into sO (tf32 mma) ----
    {
        float d2[16][4];
        #pragma unroll
        for (int a = 0; a < 16; ++a)
            #pragma unroll
            for (int e = 0; e < 4; ++e) d2[a][e] = 0.f;

        for (int chunk = 0; chunk < 8; ++chunk) {    // k-chunks of 32
            __syncthreads();
            stageB(sB, Wm, 256, chunk * 32, 0, 4, 32, tid);
            __syncthreads();
            #pragma unroll
            for (int ks = 0; ks < 4; ++ks) {
                const int kc = chunk * 32 + ks * 8;
                const float* Ap = sO + (m0 + gid) * STS + kc + ctid;
                uint32_t a0 = f2tf(Ap[0]);
                uint32_t a1 = f2tf(Ap[8 * STS]);
                uint32_t a2 = f2tf(Ap[4]);
                uint32_t a3 = f2tf(Ap[8 * STS + 4]);
                #pragma unroll
                for (int ntl = 0; ntl < 16; ++ntl) {
                    int nt = nh * 16 + ntl;
                    uint2 b = ((const uint2*)sB)[(ks * 32 + nt) * 32 + lane];
                    mma8(d2[ntl], a0, a1, a2, a3, b.x, b.y);
                }
            }
        }
        __syncthreads();   // all reads of sO complete
        {
            const int r0 = m0 + gid, r1 = r0 + 8;
            #pragma unroll
            for (int ntl = 0; ntl < 16; ++ntl) {
                int cb = (nh * 16 + ntl) * 8 + ctid * 2;
                *(float2*)(sO + r0 * STS + cb) = make_float2(d2[ntl][0], d2[ntl][1]);
                *(float2*)(sO + r1 * STS + cb) = make_float2(d2[ntl][2], d2[ntl][3]);
            }
        }
        __syncthreads();
        // LN1 in place over sO rows
        {
            const int r  = tid >> 2;
            const int c0 = (tid & 3) * 64;
            float vv[64];
            float s = 0.f, s2 = 0.f;
            #pragma unroll
            for (int j = 0; j < 64; ++j) {
                vv[j] = sO[r * STS + c0 + j];
                s += vv[j]; s2 += vv[j] * vv[j];
            }
            s  += __shfl_xor_sync(0xffffffffu, s, 1);
            s  += __shfl_xor_sync(0xffffffffu, s, 2);
            s2 += __shfl_xor_sync(0xffffffffu, s2, 1);
            s2 += __shfl_xor_sync(0xffffffffu, s2, 2);
            float mean = s * (1.f / 256.f);
            float var  = s2 * (1.f / 256.f) - mean * mean;
            float rstd = rsqrtf(var + EPS);
            #pragma unroll
            for (int j = 0; j < 64; ++j) {
                int col = c0 + j;
                sO[r * STS + col] = (vv[j] - mean) * rstd * sG1[col] + sBe1[col];
            }
        }
        __syncthreads();
    }

    // ---- Phase 3: MLP  Y = relu(cat[t,LN1] @ W1) @ W2 ; out = t + LN2(Y) ----
    {
        float y[16][4];
        #pragma unroll
        for (int a = 0; a < 16; ++a)
            #pragma unroll
            for (int e = 0; e < 4; ++e) y[a][e] = 0.f;

        for (int ht = 0; ht < 4; ++ht) {
            // (i) Htile = relu(cat @ W1[:, ht*128:+128])
            float hh[8][4];
            #pragma unroll
            for (int a = 0; a < 8; ++a)
                #pragma unroll
                for (int e = 0; e < 4; ++e) hh[a][e] = 0.f;

            for (int chunk = 0; chunk < 8; ++chunk) {   // k-chunks of 64 over K=512
                __syncthreads();
                stageB(sB, W1, 512, chunk * 64, ht * 128, 8, 16, tid);
                __syncthreads();
                const float* Abase = (chunk < 4) ? sT : sO;
                const int koff = (chunk < 4) ? chunk * 64 : (chunk - 4) * 64;
                #pragma unroll
                for (int ks = 0; ks < 8; ++ks) {
                    const int kc = koff + ks * 8;
                    const float* Ap = Abase + (m0 + gid) * STS + kc + ctid;
                    uint32_t a0 = f2tf(Ap[0]);
                    uint32_t a1 = f2tf(Ap[8 * STS]);
                    uint32_t a2 = f2tf(Ap[4]);
                    uint32_t a3 = f2tf(Ap[8 * STS + 4]);
                    #pragma unroll
                    for (int ntl = 0; ntl < 8; ++ntl) {
                        int nt = nh * 8 + ntl;
                        uint2 b = ((const uint2*)sB)[(ks * 16 + nt) * 32 + lane];
                        mma8(hh[ntl], a0, a1, a2, a3, b.x, b.y);
                    }
                }
            }
            // relu -> sH (consumers gated by the staging syncs below)
            {
                const int r0 = m0 + gid, r1 = r0 + 8;
                #pragma unroll
                for (int ntl = 0; ntl < 8; ++ntl) {
                    int cb = (nh * 8 + ntl) * 8 + ctid * 2;
                    *(float2*)(sH + r0 * 132 + cb) =
                        make_float2(fmaxf(hh[ntl][0], 0.f), fmaxf(hh[ntl][1], 0.f));
                    *(float2*)(sH + r1 * 132 + cb) =
                        make_float2(fmaxf(hh[ntl][2], 0.f), fmaxf(hh[ntl][3], 0.f));
                }
            }

            // (ii) Y += Htile @ W2[ht*128:+128, :]
            for (int chunk2 = 0; chunk2 < 4; ++chunk2) {   // k-chunks of 32 over 128
                __syncthreads();   // also publishes sH writes
                stageB(sB, W2, 256, ht * 128 + chunk2 * 32, 0, 4, 32, tid);
                __syncthreads();
                #pragma unroll
                for (int ks = 0; ks < 4; ++ks) {
                    const int kc = chunk2 * 32 + ks * 8;
                    const float* Ap = sH + (m0 + gid) * 132 + kc + ctid;
                    uint32_t a0 = f2tf(Ap[0]);
                    uint32_t a1 = f2tf(Ap[8 * 132]);
                    uint32_t a2 = f2tf(Ap[4]);
                    uint32_t a3 = f2tf(Ap[8 * 132 + 4]);
                    #pragma unroll
                    for (int ntl = 0; ntl < 16; ++ntl) {
                        int nt = nh * 16 + ntl;
                        uint2 b = ((const uint2*)sB)[(ks * 32 + nt) * 32 + lane];
                        mma8(y[ntl], a0, a1, a2, a3, b.x, b.y);
                    }
                }
            }
        }
        __syncthreads();
        // Y -> sO (sO fully consumed by now)
        {
            const int r0 = m0 + gid, r1 = r0 + 8;
            #pragma unroll
            for (int ntl = 0; ntl < 16; ++ntl) {
                int cb = (nh * 16 + ntl) * 8 + ctid * 2;
                *(float2*)(sO + r0 * STS + cb) = make_float2(y[ntl][0], y[ntl][1]);
                *(float2*)(sO + r1 * STS + cb) = make_float2(y[ntl][2], y[ntl][3]);
            }
        }
        __syncthreads();
        // LN2 + residual + store
        {
            const int r  = tid >> 2;
            const int c0 = (tid & 3) * 64;
            float vv[64];
            float s = 0.f, s2 = 0.f;
            #pragma unroll
            for (int j = 0; j < 64; ++j) {
                vv[j] = sO[r * STS + c0 + j];
                s += vv[j]; s2 += vv[j] * vv[j];
            }
            s  += __shfl_xor_sync(0xffffffffu, s, 1);
            s  += __shfl_xor_sync(0xffffffffu, s, 2);
            s2 += __shfl_xor_sync(0xffffffffu, s2, 1);
            s2 += __shfl_xor_sync(0xffffffffu, s2, 2);
            float mean = s * (1.f / 256.f);
            float var  = s2 * (1.f / 256.f) - mean * mean;
            float rstd = rsqrtf(var + EPS);
            const size_t gbase = (size_t)w * 16384;
            #pragma unroll
            for (int j = 0; j < 64; j += 4) {
                float4 o4;
                #pragma unroll
                for (int e = 0; e < 4; ++e) {
                    int col = c0 + j + e;
                    ((float*)&o4)[e] = (vv[j + e] - mean) * rstd * sG2[col] + sBe2[col]
                                       + sT[r * STS + col];
                }
                *(float4*)&out[gbase + (size_t)r * 256 + c0 + j] = o4;
            }
        }
    }
}

// writes the scalar tail outputs (nums_window=1024, h=256, w=256) if present
__global__ void tail_kernel(float* __restrict__ out, long long base, int extra)
{
    if (threadIdx.x == 0) {
        const float vals[3] = {1024.f, 256.f, 256.f};
        for (int i = 0; i < extra; ++i) out[base + i] = vals[i];
    }
}

extern "C" void kernel_launch(void* const* d_in, const int* in_sizes, int n_in,
                              void* d_out, int out_size)
{
    (void)in_sizes; (void)n_in;
    const float* x   = (const float*)d_in[0];
    const float* src = (const float*)d_in[1];
    const float* Wq  = (const float*)d_in[2];
    const float* bq  = (const float*)d_in[3];
    const float* Wk  = (const float*)d_in[4];
    const float* bk  = (const float*)d_in[5];
    const float* Wv  = (const float*)d_in[6];
    const float* bv  = (const float*)d_in[7];
    const float* Wm  = (const float*)d_in[8];
    const float* W1  = (const float*)d_in[9];
    const float* W2  = (const float*)d_in[10];
    const float* g1  = (const float*)d_in[11];
    const float* be1 = (const float*)d_in[12];
    const float* g2  = (const float*)d_in[13];
    const float* be2 = (const float*)d_in[14];
    float* out = (float*)d_out;

    cudaFuncSetAttribute(win_attn_kernel,
                         cudaFuncAttributeMaxDynamicSharedMemorySize, SMEM_BYTES);

    const long long base = 4096LL * 16384LL;   // 2 * 2048 windows * 64 * 256
    if ((long long)out_size >= base) {
        win_attn_kernel<<<4096, 256, SMEM_BYTES>>>(
            x, src, Wq, bq, Wk, bk, Wv, bv, Wm, W1, W2, g1, be1, g2, be2, out);
        long long extra = (long long)out_size - base;
        if (extra > 0) {
            if (extra > 3) extra = 3;
            tail_kernel<<<1, 32>>>(out, base, (int)extra);
        }
    }
}